// round 10
// baseline (speedup 1.0000x reference)
#include <cuda_runtime.h>
#include <cuda_fp16.h>
#include <cstdint>

#define D    128
#define LDH  136                // half row stride in smem (8-half pad, conflict-free ldmatrix)
#define TILE_B (128 * LDH * 2)  // 34816 bytes per staged 128x128 fp16 tile
#define TL   (128 * LDH)        // halfs per tile

// fp16 scratch tables (allocation-free __device__ globals)
__device__ __half g_Ktab[50000 * D];   // tanh((attr + item) @ Wk^T + bk)
__device__ __half g_A   [50000 * D];   // item @ Wv^T
__device__ __half g_B   [ 5000 * D];   // opin @ Wv^T + bv
__device__ __half g_Q   [10000 * D];   // tanh(user @ Wq^T + bq)

static __device__ __forceinline__ uint32_t smem_u32(const void* p) {
    return (uint32_t)__cvta_generic_to_shared(p);
}
static __device__ __forceinline__ void ldsm_x4(uint32_t& r0, uint32_t& r1,
                                               uint32_t& r2, uint32_t& r3, uint32_t addr) {
    asm volatile("ldmatrix.sync.aligned.m8n8.x4.shared.b16 {%0,%1,%2,%3}, [%4];"
                 : "=r"(r0), "=r"(r1), "=r"(r2), "=r"(r3) : "r"(addr));
}
static __device__ __forceinline__ void mma16816(float* d,
                                                const uint32_t* a, const uint32_t* b) {
    asm volatile("mma.sync.aligned.m16n8k16.row.col.f32.f16.f16.f32 "
                 "{%0,%1,%2,%3}, {%4,%5,%6,%7}, {%8,%9}, {%0,%1,%2,%3};"
                 : "+f"(d[0]), "+f"(d[1]), "+f"(d[2]), "+f"(d[3])
                 : "r"(a[0]), "r"(a[1]), "r"(a[2]), "r"(a[3]), "r"(b[0]), "r"(b[1]));
}
static __device__ __forceinline__ float tanha(float x) {
    float y;
    asm("tanh.approx.f32 %0, %1;" : "=f"(y) : "f"(x));
    return y;
}
static __device__ __forceinline__ __half2 tanh2(__half2 x) {
    uint32_t xi = *(uint32_t*)&x, yi;
    asm("tanh.approx.f16x2 %0, %1;" : "=r"(yi) : "r"(xi));
    return *(__half2*)&yi;
}

// Stage a 128x128 fp32 tile as hi/lo fp16 into padded smem, nth cooperating threads.
static __device__ __forceinline__ void stage_hilo_n(__half* hi, __half* lo,
    const float* __restrict__ src, int row0, int M, int lid, int nth)
{
    for (int idx = lid; idx < 128 * 32; idx += nth) {
        int r  = idx >> 5;
        int c4 = (idx & 31) << 2;
        int gr = row0 + r;
        float4 v = make_float4(0.f, 0.f, 0.f, 0.f);
        if (gr < M) v = *(const float4*)(src + (size_t)gr * D + c4);
        __half h0 = __float2half_rn(v.x), h1 = __float2half_rn(v.y);
        __half h2 = __float2half_rn(v.z), h3 = __float2half_rn(v.w);
        __half l0 = __float2half_rn(v.x - __half2float(h0));
        __half l1 = __float2half_rn(v.y - __half2float(h1));
        __half l2 = __float2half_rn(v.z - __half2float(h2));
        __half l3 = __float2half_rn(v.w - __half2float(h3));
        __half2 ph0 = __halves2half2(h0, h1), ph1 = __halves2half2(h2, h3);
        __half2 pl0 = __halves2half2(l0, l1), pl1 = __halves2half2(l2, l3);
        uint2 uh, ul;
        uh.x = *(uint32_t*)&ph0; uh.y = *(uint32_t*)&ph1;
        ul.x = *(uint32_t*)&pl0; ul.y = *(uint32_t*)&pl1;
        *(uint2*)(hi + r * LDH + c4) = uh;
        *(uint2*)(lo + r * LDH + c4) = ul;
    }
}

// All three table GEMMs in ONE launch; 256 rows per CTA (two 128-row sub-tiles).
// W conversion and effective bias are computed in-kernel (no setup launch).
__global__ void __launch_bounds__(512) tab_gemm_all(
    const float* __restrict__ item_table, const float* __restrict__ opin_table,
    const float* __restrict__ user_emb,   const float* __restrict__ attr,
    const float* __restrict__ Wq, const float* __restrict__ bq,
    const float* __restrict__ Wk, const float* __restrict__ bk,
    const float* __restrict__ Wv, const float* __restrict__ bv,
    __half* __restrict__ pK, __half* __restrict__ pA,
    __half* __restrict__ pB, __half* __restrict__ pQ,
    int n_item, int n_opi, int n_user, int nb_item, int nb_opi)
{
    extern __shared__ char smc[];
    float*  ebsm = (float*)smc;                 // 256 floats (1024 B)
    __half* Xhi  = (__half*)(smc + 1024);
    __half* Xlo  = Xhi + TL;
    __half* Wsm  = Xlo + TL;                    // up to 2 (hi,lo) W tile pairs

    const int tid  = threadIdx.x;
    const int lane = tid & 31;
    const int wid  = tid >> 5;
    const int wm   = wid >> 2;
    const int wn   = wid & 3;

    // role selection
    const int bid = blockIdx.x;
    const float *X, *W0p, *bias0;
    __half *out0, *out1 = nullptr;
    int M, rbase;
    bool two = false, tanh0;
    if (bid < nb_item) {
        X = item_table; W0p = Wk; bias0 = bk; out0 = pK; out1 = pA; M = n_item;
        rbase = bid * 256; two = true; tanh0 = true;
    } else if (bid < nb_item + nb_opi) {
        X = opin_table; W0p = Wv; bias0 = bv; out0 = pB; M = n_opi;
        rbase = (bid - nb_item) * 256; tanh0 = false;
    } else {
        X = user_emb; W0p = Wq; bias0 = bq; out0 = pQ; M = n_user;
        rbase = (bid - nb_item - nb_opi) * 256; tanh0 = true;
    }

    // split phase: warps 0-3 compute effective bias; warps 4-15 stage W (hi/lo)
    if (tid < 128) {
        float s = __ldg(bias0 + tid);
        if (two) {   // ebias_k[n] = bk[n] + attr . Wk[n,:]
            const float4* wr = (const float4*)(W0p + (size_t)tid * D);
            const float4* ar = (const float4*)attr;
            float s0 = 0.f, s1 = 0.f, s2 = 0.f, s3 = 0.f;
            #pragma unroll 8
            for (int k4 = 0; k4 < 32; k4++) {
                float4 w4 = __ldg(wr + k4);
                float4 a4 = __ldg(ar + k4);
                s0 += a4.x * w4.x; s1 += a4.y * w4.y;
                s2 += a4.z * w4.z; s3 += a4.w * w4.w;
            }
            s += (s0 + s1) + (s2 + s3);
        }
        ebsm[tid] = s;
        ebsm[128 + tid] = 0.f;
    } else {
        const int l = tid - 128;
        stage_hilo_n(Wsm, Wsm + TL, W0p, 0, 128, l, 384);
        if (two) stage_hilo_n(Wsm + 2 * TL, Wsm + 3 * TL, Wv, 0, 128, l, 384);
    }

    // ldmatrix lane-address mapping
    const int ag   = lane >> 3;
    const int arow = wm * 32 + (ag & 1) * 8 + (lane & 7);
    const int acol = (ag >> 1) * 8;
    const uint32_t aHi = smem_u32(Xhi + arow * LDH + acol);
    const uint32_t aLo = smem_u32(Xlo + arow * LDH + acol);
    const int brow = wn * 32 + (ag >> 1) * 8 + (lane & 7);
    const int bcol = (ag & 1) * 8;
    const uint32_t bOff = (uint32_t)(brow * LDH + bcol) * 2;
    const uint32_t bHi0 = smem_u32(Wsm) + bOff;
    const uint32_t bHi1 = smem_u32(Wsm + 2 * TL) + bOff;

    #pragma unroll 1
    for (int sub = 0; sub < 2; sub++) {
        const int row0 = rbase + sub * 128;
        if (row0 >= M) break;

        stage_hilo_n(Xhi, Xlo, X, row0, M, tid, 512);
        __syncthreads();   // X (and on sub0: W + ebias) visible

        float acc[2][2][4][4];   // [j][mf][nf][c]
        #pragma unroll
        for (int j = 0; j < 2; j++)
            #pragma unroll
            for (int mf = 0; mf < 2; mf++)
                #pragma unroll
                for (int nf = 0; nf < 4; nf++)
                    #pragma unroll
                    for (int c = 0; c < 4; c++) acc[j][mf][nf][c] = 0.f;

        #pragma unroll
        for (int ks = 0; ks < 8; ks++) {
            const uint32_t ko = (uint32_t)ks * 32;
            uint32_t ahi[2][4], alo[2][4];
            #pragma unroll
            for (int mf = 0; mf < 2; mf++) {
                const uint32_t mo = (uint32_t)(mf * 16 * LDH) * 2;
                ldsm_x4(ahi[mf][0], ahi[mf][1], ahi[mf][2], ahi[mf][3], aHi + mo + ko);
                ldsm_x4(alo[mf][0], alo[mf][1], alo[mf][2], alo[mf][3], aLo + mo + ko);
            }
            {   // j = 0
                uint32_t bhi[4][2], blo[4][2];
                #pragma unroll
                for (int nh = 0; nh < 2; nh++) {
                    const uint32_t no = (uint32_t)(nh * 16 * LDH) * 2;
                    ldsm_x4(bhi[nh*2][0], bhi[nh*2][1], bhi[nh*2+1][0], bhi[nh*2+1][1],
                            bHi0 + no + ko);
                    ldsm_x4(blo[nh*2][0], blo[nh*2][1], blo[nh*2+1][0], blo[nh*2+1][1],
                            bHi0 + (uint32_t)TILE_B + no + ko);
                }
                #pragma unroll
                for (int mf = 0; mf < 2; mf++)
                    #pragma unroll
                    for (int nf = 0; nf < 4; nf++) {
                        mma16816(acc[0][mf][nf], ahi[mf], bhi[nf]);
                        mma16816(acc[0][mf][nf], ahi[mf], blo[nf]);
                        mma16816(acc[0][mf][nf], alo[mf], bhi[nf]);
                    }
            }
            if (two) {   // j = 1
                uint32_t bhi[4][2], blo[4][2];
                #pragma unroll
                for (int nh = 0; nh < 2; nh++) {
                    const uint32_t no = (uint32_t)(nh * 16 * LDH) * 2;
                    ldsm_x4(bhi[nh*2][0], bhi[nh*2][1], bhi[nh*2+1][0], bhi[nh*2+1][1],
                            bHi1 + no + ko);
                    ldsm_x4(blo[nh*2][0], blo[nh*2][1], blo[nh*2+1][0], blo[nh*2+1][1],
                            bHi1 + (uint32_t)TILE_B + no + ko);
                }
                #pragma unroll
                for (int mf = 0; mf < 2; mf++)
                    #pragma unroll
                    for (int nf = 0; nf < 4; nf++) {
                        mma16816(acc[1][mf][nf], ahi[mf], bhi[nf]);
                        mma16816(acc[1][mf][nf], ahi[mf], blo[nf]);
                        mma16816(acc[1][mf][nf], alo[mf], bhi[nf]);
                    }
            }
        }
        __syncthreads();   // all ldsm done; Xhi/Xlo free for next sub-tile

        // epilogue
        const int NW = two ? 2 : 1;
        for (int j = 0; j < NW; j++) {
            __half* outp = (j == 0) ? out0 : out1;
            const bool T = (j == 0) ? tanh0 : false;
            const float* ebj = ebsm + j * 128;
            #pragma unroll
            for (int mf = 0; mf < 2; mf++) {
                const int r0 = row0 + wm * 32 + mf * 16 + (lane >> 2);
                const int r1 = r0 + 8;
                #pragma unroll
                for (int nf = 0; nf < 4; nf++) {
                    const int col = wn * 32 + nf * 8 + 2 * (lane & 3);
                    float e0 = ebj[col], e1 = ebj[col + 1];
                    float v0 = acc[j][mf][nf][0] + e0, v1 = acc[j][mf][nf][1] + e1;
                    float v2 = acc[j][mf][nf][2] + e0, v3 = acc[j][mf][nf][3] + e1;
                    if (T) { v0 = tanha(v0); v1 = tanha(v1); v2 = tanha(v2); v3 = tanha(v3); }
                    if (r0 < M) *(__half2*)(outp + (size_t)r0 * D + col) = __floats2half2_rn(v0, v1);
                    if (r1 < M) *(__half2*)(outp + (size_t)r1 * D + col) = __floats2half2_rn(v2, v3);
                }
            }
        }
    }
}

// One warp per user; 4-step pipelined, half2 dot + f16x2 tanh, fp32 accumulate.
__global__ void __launch_bounds__(256) attend_kernel(
    const int* __restrict__ item_seqs,
    const int* __restrict__ opin_seqs,
    float* __restrict__ out, int U, int L)
{
    const int gw   = (int)((blockIdx.x * blockDim.x + threadIdx.x) >> 5);
    const int lane = threadIdx.x & 31;
    if (gw >= U) return;

    const uint2* Kt = (const uint2*)g_Ktab;   // 32 uint2 per row
    const uint2* At = (const uint2*)g_A;
    const uint2* Bt = (const uint2*)g_B;

    uint2 qw = *((const uint2*)g_Q + (size_t)gw * 32 + lane);
    const __half2 qx = *reinterpret_cast<__half2*>(&qw.x);
    const __half2 qy = *reinterpret_cast<__half2*>(&qw.y);

    float4 acc = make_float4(0.f, 0.f, 0.f, 0.f);
    const int* is = item_seqs + (size_t)gw * L;
    const int* os = opin_seqs + (size_t)gw * L;

    const int Lm = L & ~3;
    for (int l = 0; l < Lm; l += 4) {
        int2 i01 = __ldg((const int2*)(is + l));
        int2 i23 = __ldg((const int2*)(is + l + 2));
        int2 o01 = __ldg((const int2*)(os + l));
        int2 o23 = __ldg((const int2*)(os + l + 2));
        int ii[4] = {i01.x, i01.y, i23.x, i23.y};
        int oo[4] = {o01.x, o01.y, o23.x, o23.y};

        uint2 kw[4], aw[4], bw[4];
        #pragma unroll
        for (int t = 0; t < 4; t++) {
            kw[t] = __ldg(Kt + (size_t)ii[t] * 32 + lane);
            aw[t] = __ldg(At + (size_t)ii[t] * 32 + lane);
            bw[t] = __ldg(Bt + (size_t)oo[t] * 32 + lane);
        }

        float w[4];
        #pragma unroll
        for (int t = 0; t < 4; t++) {
            __half2 kx = *reinterpret_cast<__half2*>(&kw[t].x);
            __half2 ky = *reinterpret_cast<__half2*>(&kw[t].y);
            __half2 dp = __hfma2(ky, qy, __hmul2(kx, qx));
            float2 df = __half22float2(dp);
            w[t] = df.x + df.y;
        }
        #pragma unroll
        for (int s = 16; s; s >>= 1) {
            w[0] += __shfl_xor_sync(0xffffffffu, w[0], s);
            w[1] += __shfl_xor_sync(0xffffffffu, w[1], s);
            w[2] += __shfl_xor_sync(0xffffffffu, w[2], s);
            w[3] += __shfl_xor_sync(0xffffffffu, w[3], s);
        }
        #pragma unroll
        for (int t = 0; t < 4; t++) {
            float wt = (ii[t] > 0) ? w[t] : 0.f;
            __half2 sx = tanh2(__hadd2(*reinterpret_cast<__half2*>(&aw[t].x),
                                       *reinterpret_cast<__half2*>(&bw[t].x)));
            __half2 sy = tanh2(__hadd2(*reinterpret_cast<__half2*>(&aw[t].y),
                                       *reinterpret_cast<__half2*>(&bw[t].y)));
            float2 fx = __half22float2(sx), fy = __half22float2(sy);
            acc.x += wt * fx.x;
            acc.y += wt * fx.y;
            acc.z += wt * fy.x;
            acc.w += wt * fy.y;
        }
    }
    for (int l = Lm; l < L; ++l) {
        int i = __ldg(is + l);
        int o = __ldg(os + l);
        uint2 kw = __ldg(Kt + (size_t)i * 32 + lane);
        uint2 aw = __ldg(At + (size_t)i * 32 + lane);
        uint2 bw = __ldg(Bt + (size_t)o * 32 + lane);
        __half2 kx = *reinterpret_cast<__half2*>(&kw.x);
        __half2 ky = *reinterpret_cast<__half2*>(&kw.y);
        __half2 dp = __hfma2(ky, qy, __hmul2(kx, qx));
        float2 df = __half22float2(dp);
        float w = df.x + df.y;
        #pragma unroll
        for (int s = 16; s; s >>= 1) w += __shfl_xor_sync(0xffffffffu, w, s);
        w = (i > 0) ? w : 0.f;
        __half2 sx = tanh2(__hadd2(*reinterpret_cast<__half2*>(&aw.x),
                                   *reinterpret_cast<__half2*>(&bw.x)));
        __half2 sy = tanh2(__hadd2(*reinterpret_cast<__half2*>(&aw.y),
                                   *reinterpret_cast<__half2*>(&bw.y)));
        float2 fx = __half22float2(sx), fy = __half22float2(sy);
        acc.x += w * fx.x;
        acc.y += w * fx.y;
        acc.z += w * fy.x;
        acc.w += w * fy.y;
    }
    *(float4*)(out + (size_t)gw * D + lane * 4) = acc;
}

extern "C" void kernel_launch(void* const* d_in, const int* in_sizes, int n_in,
                              void* d_out, int out_size)
{
    const float* item_table = (const float*)d_in[0];
    const float* opin_table = (const float*)d_in[1];
    const float* user_emb   = (const float*)d_in[2];
    const float* attr       = (const float*)d_in[3];
    const float* Wq         = (const float*)d_in[4];
    const float* bq         = (const float*)d_in[5];
    const float* Wk         = (const float*)d_in[6];
    const float* bk         = (const float*)d_in[7];
    const float* Wv         = (const float*)d_in[8];
    const float* bv         = (const float*)d_in[9];
    const int*   item_seqs  = (const int*)d_in[10];
    const int*   opin_seqs  = (const int*)d_in[11];
    float*       out        = (float*)d_out;

    const int n_item = in_sizes[0] / D;
    const int n_opi  = in_sizes[1] / D;
    const int U      = in_sizes[2] / D;
    const int L      = in_sizes[10] / U;

    __half *pK, *pA, *pB, *pQ;
    cudaGetSymbolAddress((void**)&pK, g_Ktab);
    cudaGetSymbolAddress((void**)&pA, g_A);
    cudaGetSymbolAddress((void**)&pB, g_B);
    cudaGetSymbolAddress((void**)&pQ, g_Q);

    const int nb_item = (n_item + 255) / 256;
    const int nb_opi  = (n_opi + 255) / 256;
    const int nb_user = (U + 255) / 256;

    const int smemB = 1024 + 6 * TILE_B;   // 209920 B
    cudaFuncSetAttribute((const void*)tab_gemm_all,
                         cudaFuncAttributeMaxDynamicSharedMemorySize, smemB);

    tab_gemm_all<<<nb_item + nb_opi + nb_user, 512, smemB>>>(
        item_table, opin_table, user_emb, attr,
        Wq, bq, Wk, bk, Wv, bv,
        pK, pA, pB, pQ, n_item, n_opi, U, nb_item, nb_opi);

    const int threads = 256;
    const int blocks  = (U * 32 + threads - 1) / threads;
    attend_kernel<<<blocks, threads>>>(item_seqs, opin_seqs, out, U, L);
}

// round 11
// speedup vs baseline: 1.1961x; 1.1961x over previous
#include <cuda_runtime.h>
#include <cuda_fp16.h>
#include <cstdint>

#define D    128
#define LDH  136                // half row stride in smem (8-half pad, conflict-free ldmatrix)
#define TILE_B (128 * LDH * 2)  // 34816 bytes per staged 128x128 fp16 tile
#define TL   (128 * LDH)

// fp16 scratch tables (allocation-free __device__ globals)
__device__ __half g_Ktab[50000 * D];   // tanh((attr + item) @ Wk^T + bk)
__device__ __half g_A   [50000 * D];   // item @ Wv^T
__device__ __half g_B   [ 5000 * D];   // opin @ Wv^T + bv
__device__ __half g_Q   [10000 * D];   // tanh(user @ Wq^T + bq)

// Preconverted weights (hi/lo fp16) + effective biases
__device__ __half g_Wh[3][128 * 128];  // 0: Wk, 1: Wv, 2: Wq
__device__ __half g_Wl[3][128 * 128];
__device__ float  g_eb[3][128];        // 0: bk + attr.Wk[n,:], 1: bv, 2: bq

static __device__ __forceinline__ uint32_t smem_u32(const void* p) {
    return (uint32_t)__cvta_generic_to_shared(p);
}
static __device__ __forceinline__ void ldsm_x4(uint32_t& r0, uint32_t& r1,
                                               uint32_t& r2, uint32_t& r3, uint32_t addr) {
    asm volatile("ldmatrix.sync.aligned.m8n8.x4.shared.b16 {%0,%1,%2,%3}, [%4];"
                 : "=r"(r0), "=r"(r1), "=r"(r2), "=r"(r3) : "r"(addr));
}
static __device__ __forceinline__ void mma16816(float* d,
                                                const uint32_t* a, const uint32_t* b) {
    asm volatile("mma.sync.aligned.m16n8k16.row.col.f32.f16.f16.f32 "
                 "{%0,%1,%2,%3}, {%4,%5,%6,%7}, {%8,%9}, {%0,%1,%2,%3};"
                 : "+f"(d[0]), "+f"(d[1]), "+f"(d[2]), "+f"(d[3])
                 : "r"(a[0]), "r"(a[1]), "r"(a[2]), "r"(a[3]), "r"(b[0]), "r"(b[1]));
}
static __device__ __forceinline__ float tanha(float x) {
    float y;
    asm("tanh.approx.f32 %0, %1;" : "=f"(y) : "f"(x));
    return y;
}
static __device__ __forceinline__ __half2 tanh2(__half2 x) {
    uint32_t xi = *(uint32_t*)&x, yi;
    asm("tanh.approx.f16x2 %0, %1;" : "=r"(yi) : "r"(xi));
    return *(__half2*)&yi;
}

// ---------------- setup: preconvert W -> fp16 hi/lo, compute effective biases.
// grid = 51: blocks 0-47 convert W slices; 48-49 ebias j=0 (warp dot); 50 copies bv/bq.
__global__ void __launch_bounds__(256) setup_kernel(
    const float* __restrict__ Wk, const float* __restrict__ bk,
    const float* __restrict__ Wv, const float* __restrict__ bv,
    const float* __restrict__ Wq, const float* __restrict__ bq,
    const float* __restrict__ attr)
{
    const int b   = blockIdx.x;
    const int tid = threadIdx.x;

    if (b < 48) {
        const int j     = b >> 4;
        const int slice = b & 15;
        const float* W = (j == 0) ? Wk : (j == 1) ? Wv : Wq;
        const int e4 = (slice * 256 + tid) * 4;
        float4 v = *(const float4*)(W + e4);
        __half h0 = __float2half_rn(v.x), h1 = __float2half_rn(v.y);
        __half h2 = __float2half_rn(v.z), h3 = __float2half_rn(v.w);
        __half l0 = __float2half_rn(v.x - __half2float(h0));
        __half l1 = __float2half_rn(v.y - __half2float(h1));
        __half l2 = __float2half_rn(v.z - __half2float(h2));
        __half l3 = __float2half_rn(v.w - __half2float(h3));
        __half2 ph0 = __halves2half2(h0, h1), ph1 = __halves2half2(h2, h3);
        __half2 pl0 = __halves2half2(l0, l1), pl1 = __halves2half2(l2, l3);
        uint2 uh, ul;
        uh.x = *(uint32_t*)&ph0; uh.y = *(uint32_t*)&ph1;
        ul.x = *(uint32_t*)&pl0; ul.y = *(uint32_t*)&pl1;
        *(uint2*)(&g_Wh[j][e4]) = uh;
        *(uint2*)(&g_Wl[j][e4]) = ul;
    } else if (b < 50) {
        const int wid = tid >> 5, lane = tid & 31;
        const float4 a4 = *(const float4*)(attr + lane * 4);
        #pragma unroll
        for (int t = 0; t < 8; t++) {
            const int n = (b - 48) * 64 + wid * 8 + t;
            float4 w4 = *(const float4*)(Wk + (size_t)n * D + lane * 4);
            float s = a4.x * w4.x + a4.y * w4.y + a4.z * w4.z + a4.w * w4.w;
            #pragma unroll
            for (int sh = 16; sh; sh >>= 1) s += __shfl_xor_sync(0xffffffffu, s, sh);
            if (lane == 0) g_eb[0][n] = s + __ldg(bk + n);
        }
    } else {
        if (tid < 128)      g_eb[1][tid]       = __ldg(bv + tid);
        else                g_eb[2][tid - 128] = __ldg(bq + tid - 128);
    }
}

// Stage a 128x128 fp32 tile as fp16 (hi only) into padded smem (512 threads).
static __device__ __forceinline__ void stage_hi(__half* hi,
    const float* __restrict__ src, int row0, int M, int tid)
{
    #pragma unroll
    for (int idx = tid; idx < 128 * 32; idx += 512) {
        int r  = idx >> 5;
        int c4 = (idx & 31) << 2;
        int gr = row0 + r;
        float4 v = make_float4(0.f, 0.f, 0.f, 0.f);
        if (gr < M) v = *(const float4*)(src + (size_t)gr * D + c4);
        __half2 ph0 = __floats2half2_rn(v.x, v.y);
        __half2 ph1 = __floats2half2_rn(v.z, v.w);
        uint2 uh;
        uh.x = *(uint32_t*)&ph0; uh.y = *(uint32_t*)&ph1;
        *(uint2*)(hi + r * LDH + c4) = uh;
    }
}

// Copy a preconverted 128x128 fp16 tile into padded smem.
static __device__ __forceinline__ void stage_w(__half* dst, const __half* __restrict__ src,
                                               int tid)
{
    #pragma unroll
    for (int idx = tid; idx < 128 * 16; idx += 512) {
        int r = idx >> 4;
        int c = (idx & 15) << 3;
        *(uint4*)(dst + r * LDH + c) = *(const uint4*)(src + r * 128 + c);
    }
}

// All three table GEMMs in ONE launch; 256 rows per CTA (two 128-row sub-tiles).
// 2-pass precision: Xhi*(Whi + Wlo) = Xhi*W  (omitted Xlo*W term ~2^-12 rel).
__global__ void __launch_bounds__(512) tab_gemm_all(
    const float* __restrict__ item_table, const float* __restrict__ opin_table,
    const float* __restrict__ user_emb,
    __half* __restrict__ pK, __half* __restrict__ pA,
    __half* __restrict__ pB, __half* __restrict__ pQ,
    int n_item, int n_opi, int n_user, int nb_item, int nb_opi)
{
    extern __shared__ char smc[];
    __half* Xhi = (__half*)smc;
    __half* Wsm = Xhi + TL;    // up to 2 (hi,lo) W tile pairs

    const int tid  = threadIdx.x;
    const int lane = tid & 31;
    const int wid  = tid >> 5;
    const int wm   = wid >> 2;
    const int wn   = wid & 3;

    // role selection
    const int bid = blockIdx.x;
    const float* X;
    __half *out0, *out1 = nullptr;
    int M, rbase, jw0, jw1 = -1;
    bool two = false, tanh0;
    if (bid < nb_item) {
        X = item_table; out0 = pK; out1 = pA; M = n_item;
        rbase = bid * 256; jw0 = 0; jw1 = 1; two = true; tanh0 = true;
    } else if (bid < nb_item + nb_opi) {
        X = opin_table; out0 = pB; M = n_opi;
        rbase = (bid - nb_item) * 256; jw0 = 1; tanh0 = false;
    } else {
        X = user_emb; out0 = pQ; M = n_user;
        rbase = (bid - nb_item - nb_opi) * 256; jw0 = 2; tanh0 = true;
    }

    // stage W tiles (from preconverted fp16 globals)
    stage_w(Wsm,             g_Wh[jw0], tid);
    stage_w(Wsm + TL,        g_Wl[jw0], tid);
    if (two) {
        stage_w(Wsm + 2 * TL, g_Wh[jw1], tid);
        stage_w(Wsm + 3 * TL, g_Wl[jw1], tid);
    }

    // ldmatrix lane-address mapping
    const int ag   = lane >> 3;
    const int arow = wm * 32 + (ag & 1) * 8 + (lane & 7);
    const int acol = (ag >> 1) * 8;
    const uint32_t aHi = smem_u32(Xhi + arow * LDH + acol);
    const int brow = wn * 32 + (ag >> 1) * 8 + (lane & 7);
    const int bcol = (ag & 1) * 8;
    const uint32_t bOff = (uint32_t)(brow * LDH + bcol) * 2;
    const uint32_t bHi0 = smem_u32(Wsm) + bOff;
    const uint32_t bHi1 = smem_u32(Wsm + 2 * TL) + bOff;

    #pragma unroll 1
    for (int sub = 0; sub < 2; sub++) {
        const int row0 = rbase + sub * 128;
        if (row0 >= M) break;

        stage_hi(Xhi, X, row0, M, tid);
        __syncthreads();

        float acc[2][2][4][4];   // [j][mf][nf][c]
        #pragma unroll
        for (int j = 0; j < 2; j++)
            #pragma unroll
            for (int mf = 0; mf < 2; mf++)
                #pragma unroll
                for (int nf = 0; nf < 4; nf++)
                    #pragma unroll
                    for (int c = 0; c < 4; c++) acc[j][mf][nf][c] = 0.f;

        #pragma unroll
        for (int ks = 0; ks < 8; ks++) {
            const uint32_t ko = (uint32_t)ks * 32;
            uint32_t ahi[2][4];
            #pragma unroll
            for (int mf = 0; mf < 2; mf++) {
                const uint32_t mo = (uint32_t)(mf * 16 * LDH) * 2;
                ldsm_x4(ahi[mf][0], ahi[mf][1], ahi[mf][2], ahi[mf][3], aHi + mo + ko);
            }
            {   // j = 0
                uint32_t bhi[4][2], blo[4][2];
                #pragma unroll
                for (int nh = 0; nh < 2; nh++) {
                    const uint32_t no = (uint32_t)(nh * 16 * LDH) * 2;
                    ldsm_x4(bhi[nh*2][0], bhi[nh*2][1], bhi[nh*2+1][0], bhi[nh*2+1][1],
                            bHi0 + no + ko);
                    ldsm_x4(blo[nh*2][0], blo[nh*2][1], blo[nh*2+1][0], blo[nh*2+1][1],
                            bHi0 + (uint32_t)TILE_B + no + ko);
                }
                #pragma unroll
                for (int mf = 0; mf < 2; mf++)
                    #pragma unroll
                    for (int nf = 0; nf < 4; nf++) {
                        mma16816(acc[0][mf][nf], ahi[mf], bhi[nf]);
                        mma16816(acc[0][mf][nf], ahi[mf], blo[nf]);
                    }
            }
            if (two) {   // j = 1
                uint32_t bhi[4][2], blo[4][2];
                #pragma unroll
                for (int nh = 0; nh < 2; nh++) {
                    const uint32_t no = (uint32_t)(nh * 16 * LDH) * 2;
                    ldsm_x4(bhi[nh*2][0], bhi[nh*2][1], bhi[nh*2+1][0], bhi[nh*2+1][1],
                            bHi1 + no + ko);
                    ldsm_x4(blo[nh*2][0], blo[nh*2][1], blo[nh*2+1][0], blo[nh*2+1][1],
                            bHi1 + (uint32_t)TILE_B + no + ko);
                }
                #pragma unroll
                for (int mf = 0; mf < 2; mf++)
                    #pragma unroll
                    for (int nf = 0; nf < 4; nf++) {
                        mma16816(acc[1][mf][nf], ahi[mf], bhi[nf]);
                        mma16816(acc[1][mf][nf], ahi[mf], blo[nf]);
                    }
            }
        }
        __syncthreads();   // all ldsm done; Xhi free for next sub-tile

        // epilogue
        const int NW = two ? 2 : 1;
        for (int j = 0; j < NW; j++) {
            __half* outp = (j == 0) ? out0 : out1;
            const bool T = (j == 0) ? tanh0 : false;
            const bool hasb = (j == 0);
            const float* ebj = g_eb[(j == 0) ? jw0 : jw1];
            #pragma unroll
            for (int mf = 0; mf < 2; mf++) {
                const int r0 = row0 + wm * 32 + mf * 16 + (lane >> 2);
                const int r1 = r0 + 8;
                #pragma unroll
                for (int nf = 0; nf < 4; nf++) {
                    const int col = wn * 32 + nf * 8 + 2 * (lane & 3);
                    float e0 = hasb ? __ldg(ebj + col)     : 0.f;
                    float e1 = hasb ? __ldg(ebj + col + 1) : 0.f;
                    float v0 = acc[j][mf][nf][0] + e0, v1 = acc[j][mf][nf][1] + e1;
                    float v2 = acc[j][mf][nf][2] + e0, v3 = acc[j][mf][nf][3] + e1;
                    if (T) { v0 = tanha(v0); v1 = tanha(v1); v2 = tanha(v2); v3 = tanha(v3); }
                    if (r0 < M) *(__half2*)(outp + (size_t)r0 * D + col) = __floats2half2_rn(v0, v1);
                    if (r1 < M) *(__half2*)(outp + (size_t)r1 * D + col) = __floats2half2_rn(v2, v3);
                }
            }
        }
    }
}

// One warp per user; 4-step pipelined; fp32 dot, f16x2 tanh, fp32 accumulate.
__global__ void __launch_bounds__(256) attend_kernel(
    const int* __restrict__ item_seqs,
    const int* __restrict__ opin_seqs,
    float* __restrict__ out, int U, int L)
{
    const int gw   = (int)((blockIdx.x * blockDim.x + threadIdx.x) >> 5);
    const int lane = threadIdx.x & 31;
    if (gw >= U) return;

    const uint2* Kt = (const uint2*)g_Ktab;   // 32 uint2 per row
    const uint2* At = (const uint2*)g_A;
    const uint2* Bt = (const uint2*)g_B;

    uint2 qw = *((const uint2*)g_Q + (size_t)gw * 32 + lane);
    float2 q01 = __half22float2(*reinterpret_cast<__half2*>(&qw.x));
    float2 q23 = __half22float2(*reinterpret_cast<__half2*>(&qw.y));

    float4 acc = make_float4(0.f, 0.f, 0.f, 0.f);
    const int* is = item_seqs + (size_t)gw * L;
    const int* os = opin_seqs + (size_t)gw * L;

    const int Lm = L & ~3;
    for (int l = 0; l < Lm; l += 4) {
        int2 i01 = __ldg((const int2*)(is + l));
        int2 i23 = __ldg((const int2*)(is + l + 2));
        int2 o01 = __ldg((const int2*)(os + l));
        int2 o23 = __ldg((const int2*)(os + l + 2));
        int ii[4] = {i01.x, i01.y, i23.x, i23.y};
        int oo[4] = {o01.x, o01.y, o23.x, o23.y};

        uint2 kw[4], aw[4], bw[4];
        #pragma unroll
        for (int t = 0; t < 4; t++) {
            kw[t] = __ldg(Kt + (size_t)ii[t] * 32 + lane);
            aw[t] = __ldg(At + (size_t)ii[t] * 32 + lane);
            bw[t] = __ldg(Bt + (size_t)oo[t] * 32 + lane);
        }

        float w[4];
        #pragma unroll
        for (int t = 0; t < 4; t++) {
            float2 k01 = __half22float2(*reinterpret_cast<__half2*>(&kw[t].x));
            float2 k23 = __half22float2(*reinterpret_cast<__half2*>(&kw[t].y));
            w[t] = q01.x * k01.x + q01.y * k01.y + q23.x * k23.x + q23.y * k23.y;
        }
        #pragma unroll
        for (int s = 16; s; s >>= 1) {
            w[0] += __shfl_xor_sync(0xffffffffu, w[0], s);
            w[1] += __shfl_xor_sync(0xffffffffu, w[1], s);
            w[2] += __shfl_xor_sync(0xffffffffu, w[2], s);
            w[3] += __shfl_xor_sync(0xffffffffu, w[3], s);
        }
        #pragma unroll
        for (int t = 0; t < 4; t++) {
            float wt = (ii[t] > 0) ? w[t] : 0.f;
            __half2 sx = tanh2(__hadd2(*reinterpret_cast<__half2*>(&aw[t].x),
                                       *reinterpret_cast<__half2*>(&bw[t].x)));
            __half2 sy = tanh2(__hadd2(*reinterpret_cast<__half2*>(&aw[t].y),
                                       *reinterpret_cast<__half2*>(&bw[t].y)));
            float2 fx = __half22float2(sx), fy = __half22float2(sy);
            acc.x += wt * fx.x;
            acc.y += wt * fx.y;
            acc.z += wt * fy.x;
            acc.w += wt * fy.y;
        }
    }
    for (int l = Lm; l < L; ++l) {
        int i = __ldg(is + l);
        int o = __ldg(os + l);
        uint2 kw = __ldg(Kt + (size_t)i * 32 + lane);
        uint2 aw = __ldg(At + (size_t)i * 32 + lane);
        uint2 bw = __ldg(Bt + (size_t)o * 32 + lane);
        float2 k01 = __half22float2(*reinterpret_cast<__half2*>(&kw.x));
        float2 k23 = __half22float2(*reinterpret_cast<__half2*>(&kw.y));
        float w = q01.x * k01.x + q01.y * k01.y + q23.x * k23.x + q23.y * k23.y;
        #pragma unroll
        for (int s = 16; s; s >>= 1) w += __shfl_xor_sync(0xffffffffu, w, s);
        w = (i > 0) ? w : 0.f;
        __half2 sx = tanh2(__hadd2(*reinterpret_cast<__half2*>(&aw.x),
                                   *reinterpret_cast<__half2*>(&bw.x)));
        __half2 sy = tanh2(__hadd2(*reinterpret_cast<__half2*>(&aw.y),
                                   *reinterpret_cast<__half2*>(&bw.y)));
        float2 fx = __half22float2(sx), fy = __half22float2(sy);
        acc.x += w * fx.x;
        acc.y += w * fx.y;
        acc.z += w * fy.x;
        acc.w += w * fy.y;
    }
    *(float4*)(out + (size_t)gw * D + lane * 4) = acc;
}

extern "C" void kernel_launch(void* const* d_in, const int* in_sizes, int n_in,
                              void* d_out, int out_size)
{
    const float* item_table = (const float*)d_in[0];
    const float* opin_table = (const float*)d_in[1];
    const float* user_emb   = (const float*)d_in[2];
    const float* attr       = (const float*)d_in[3];
    const float* Wq         = (const float*)d_in[4];
    const float* bq         = (const float*)d_in[5];
    const float* Wk         = (const float*)d_in[6];
    const float* bk         = (const float*)d_in[7];
    const float* Wv         = (const float*)d_in[8];
    const float* bv         = (const float*)d_in[9];
    const int*   item_seqs  = (const int*)d_in[10];
    const int*   opin_seqs  = (const int*)d_in[11];
    float*       out        = (float*)d_out;

    const int n_item = in_sizes[0] / D;
    const int n_opi  = in_sizes[1] / D;
    const int U      = in_sizes[2] / D;
    const int L      = in_sizes[10] / U;

    __half *pK, *pA, *pB, *pQ;
    cudaGetSymbolAddress((void**)&pK, g_Ktab);
    cudaGetSymbolAddress((void**)&pA, g_A);
    cudaGetSymbolAddress((void**)&pB, g_B);
    cudaGetSymbolAddress((void**)&pQ, g_Q);

    const int nb_item = (n_item + 255) / 256;
    const int nb_opi  = (n_opi + 255) / 256;
    const int nb_user = (U + 255) / 256;

    const int smemB = 5 * TILE_B;   // 174080 B
    cudaFuncSetAttribute((const void*)tab_gemm_all,
                         cudaFuncAttributeMaxDynamicSharedMemorySize, smemB);

    setup_kernel<<<51, 256>>>(Wk, bk, Wv, bv, Wq, bq, attr);

    tab_gemm_all<<<nb_item + nb_opi + nb_user, 512, smemB>>>(
        item_table, opin_table, user_emb,
        pK, pA, pB, pQ, n_item, n_opi, U, nb_item, nb_opi);

    const int threads = 256;
    const int blocks  = (U * 32 + threads - 1) / threads;
    attend_kernel<<<blocks, threads>>>(item_seqs, opin_seqs, out, U, L);
}

// round 12
// speedup vs baseline: 1.2694x; 1.0613x over previous
#include <cuda_runtime.h>
#include <cuda_fp16.h>
#include <cstdint>

#define D    128
#define LDH  136                // half row stride in smem (8-half pad, conflict-free ldmatrix)
#define TILE_B (128 * LDH * 2)  // 34816 bytes per staged 128x128 fp16 tile
#define TL   (128 * LDH)

// fp16 scratch tables (allocation-free __device__ globals)
__device__ __half g_Ktab[50000 * D];   // tanh((attr + item) @ Wk^T + bk)
__device__ __half g_A   [50000 * D];   // item @ Wv^T
__device__ __half g_B   [ 5000 * D];   // opin @ Wv^T + bv
__device__ __half g_Q   [10000 * D];   // tanh(user @ Wq^T + bq)

// Preconverted weights (hi/lo fp16) + effective biases
__device__ __half g_Wh[3][128 * 128];  // 0: Wk, 1: Wv, 2: Wq
__device__ __half g_Wl[3][128 * 128];
__device__ float  g_eb[4][128];        // 0: bk + attr.Wk, 1: bv, 2: bq, 3: zeros

static __device__ __forceinline__ uint32_t smem_u32(const void* p) {
    return (uint32_t)__cvta_generic_to_shared(p);
}
static __device__ __forceinline__ void ldsm_x4(uint32_t& r0, uint32_t& r1,
                                               uint32_t& r2, uint32_t& r3, uint32_t addr) {
    asm volatile("ldmatrix.sync.aligned.m8n8.x4.shared.b16 {%0,%1,%2,%3}, [%4];"
                 : "=r"(r0), "=r"(r1), "=r"(r2), "=r"(r3) : "r"(addr));
}
static __device__ __forceinline__ void mma16816(float* d,
                                                const uint32_t* a, const uint32_t* b) {
    asm volatile("mma.sync.aligned.m16n8k16.row.col.f32.f16.f16.f32 "
                 "{%0,%1,%2,%3}, {%4,%5,%6,%7}, {%8,%9}, {%0,%1,%2,%3};"
                 : "+f"(d[0]), "+f"(d[1]), "+f"(d[2]), "+f"(d[3])
                 : "r"(a[0]), "r"(a[1]), "r"(a[2]), "r"(a[3]), "r"(b[0]), "r"(b[1]));
}
static __device__ __forceinline__ float tanha(float x) {
    float y;
    asm("tanh.approx.f32 %0, %1;" : "=f"(y) : "f"(x));
    return y;
}
static __device__ __forceinline__ __half2 tanh2(__half2 x) {
    uint32_t xi = *(uint32_t*)&x, yi;
    asm("tanh.approx.f16x2 %0, %1;" : "=r"(yi) : "r"(xi));
    return *(__half2*)&yi;
}

// ---------------- setup: preconvert W -> fp16 hi/lo, compute effective biases.
__global__ void __launch_bounds__(256) setup_kernel(
    const float* __restrict__ Wk, const float* __restrict__ bk,
    const float* __restrict__ Wv, const float* __restrict__ bv,
    const float* __restrict__ Wq, const float* __restrict__ bq,
    const float* __restrict__ attr)
{
    const int b   = blockIdx.x;
    const int tid = threadIdx.x;

    if (b < 48) {
        const int j     = b >> 4;
        const int slice = b & 15;
        const float* W = (j == 0) ? Wk : (j == 1) ? Wv : Wq;
        const int e4 = (slice * 256 + tid) * 4;
        float4 v = *(const float4*)(W + e4);
        __half h0 = __float2half_rn(v.x), h1 = __float2half_rn(v.y);
        __half h2 = __float2half_rn(v.z), h3 = __float2half_rn(v.w);
        __half l0 = __float2half_rn(v.x - __half2float(h0));
        __half l1 = __float2half_rn(v.y - __half2float(h1));
        __half l2 = __float2half_rn(v.z - __half2float(h2));
        __half l3 = __float2half_rn(v.w - __half2float(h3));
        __half2 ph0 = __halves2half2(h0, h1), ph1 = __halves2half2(h2, h3);
        __half2 pl0 = __halves2half2(l0, l1), pl1 = __halves2half2(l2, l3);
        uint2 uh, ul;
        uh.x = *(uint32_t*)&ph0; uh.y = *(uint32_t*)&ph1;
        ul.x = *(uint32_t*)&pl0; ul.y = *(uint32_t*)&pl1;
        *(uint2*)(&g_Wh[j][e4]) = uh;
        *(uint2*)(&g_Wl[j][e4]) = ul;
    } else if (b < 50) {
        const int wid = tid >> 5, lane = tid & 31;
        const float4 a4 = *(const float4*)(attr + lane * 4);
        #pragma unroll
        for (int t = 0; t < 8; t++) {
            const int n = (b - 48) * 64 + wid * 8 + t;
            float4 w4 = *(const float4*)(Wk + (size_t)n * D + lane * 4);
            float s = a4.x * w4.x + a4.y * w4.y + a4.z * w4.z + a4.w * w4.w;
            #pragma unroll
            for (int sh = 16; sh; sh >>= 1) s += __shfl_xor_sync(0xffffffffu, s, sh);
            if (lane == 0) g_eb[0][n] = s + __ldg(bk + n);
        }
    } else {
        if (tid < 128) g_eb[1][tid]       = __ldg(bv + tid);
        else           g_eb[2][tid - 128] = __ldg(bq + tid - 128);
        g_eb[3][tid & 127] = 0.f;   // zero bias row (A output)
    }
}

// Stage a 128x128 fp32 tile as fp16 (hi only) into padded smem (512 threads).
static __device__ __forceinline__ void stage_hi(__half* hi,
    const float* __restrict__ src, int row0, int M, int tid)
{
    #pragma unroll
    for (int idx = tid; idx < 128 * 32; idx += 512) {
        int r  = idx >> 5;
        int c4 = (idx & 31) << 2;
        int gr = row0 + r;
        float4 v = make_float4(0.f, 0.f, 0.f, 0.f);
        if (gr < M) v = *(const float4*)(src + (size_t)gr * D + c4);
        __half2 ph0 = __floats2half2_rn(v.x, v.y);
        __half2 ph1 = __floats2half2_rn(v.z, v.w);
        uint2 uh;
        uh.x = *(uint32_t*)&ph0; uh.y = *(uint32_t*)&ph1;
        *(uint2*)(hi + r * LDH + c4) = uh;
    }
}

// Copy a preconverted 128x128 fp16 tile into padded smem.
static __device__ __forceinline__ void stage_w(__half* dst, const __half* __restrict__ src,
                                               int tid)
{
    #pragma unroll
    for (int idx = tid; idx < 128 * 16; idx += 512) {
        int r = idx >> 4;
        int c = (idx & 15) << 3;
        *(uint4*)(dst + r * LDH + c) = *(const uint4*)(src + r * 128 + c);
    }
}

// One output per CTA (uniform role), 256 rows per CTA (two 128-row sub-tiles).
// 2-pass precision: Xhi*(Whi + Wlo) = Xhi*W. smem = 3 tiles -> 2 CTAs/SM.
__global__ void __launch_bounds__(512, 2) tab_gemm_all(
    const float* __restrict__ item_table, const float* __restrict__ opin_table,
    const float* __restrict__ user_emb,
    __half* __restrict__ pK, __half* __restrict__ pA,
    __half* __restrict__ pB, __half* __restrict__ pQ,
    int n_item, int n_opi, int n_user, int nbK, int nbA, int nbB)
{
    extern __shared__ char smc[];
    __half* Xhi = (__half*)smc;
    __half* Whi = Xhi + TL;
    __half* Wlo = Whi + TL;

    const int tid  = threadIdx.x;
    const int lane = tid & 31;
    const int wid  = tid >> 5;
    const int wm   = wid >> 2;
    const int wn   = wid & 3;

    // uniform role selection
    const int bid = blockIdx.x;
    const float* X;
    __half* outp;
    int M, rbase, jw, je;
    bool dotanh;
    if (bid < nbK) {
        X = item_table; outp = pK; M = n_item; rbase = bid * 256;
        jw = 0; je = 0; dotanh = true;
    } else if (bid < nbK + nbA) {
        X = item_table; outp = pA; M = n_item; rbase = (bid - nbK) * 256;
        jw = 1; je = 3; dotanh = false;
    } else if (bid < nbK + nbA + nbB) {
        X = opin_table; outp = pB; M = n_opi; rbase = (bid - nbK - nbA) * 256;
        jw = 1; je = 1; dotanh = false;
    } else {
        X = user_emb; outp = pQ; M = n_user; rbase = (bid - nbK - nbA - nbB) * 256;
        jw = 2; je = 2; dotanh = true;
    }

    stage_w(Whi, g_Wh[jw], tid);
    stage_w(Wlo, g_Wl[jw], tid);

    // ldmatrix lane-address mapping
    const int ag   = lane >> 3;
    const int arow = wm * 32 + (ag & 1) * 8 + (lane & 7);
    const int acol = (ag >> 1) * 8;
    const uint32_t aHi = smem_u32(Xhi + arow * LDH + acol);
    const int brow = wn * 32 + (ag >> 1) * 8 + (lane & 7);
    const int bcol = (ag & 1) * 8;
    const uint32_t bHi = smem_u32(Whi + brow * LDH + bcol);
    const uint32_t bLo = smem_u32(Wlo + brow * LDH + bcol);

    #pragma unroll 1
    for (int sub = 0; sub < 2; sub++) {
        const int row0 = rbase + sub * 128;
        if (row0 >= M) break;

        stage_hi(Xhi, X, row0, M, tid);
        __syncthreads();

        float acc[2][4][4];   // [mf][nf][c]
        #pragma unroll
        for (int mf = 0; mf < 2; mf++)
            #pragma unroll
            for (int nf = 0; nf < 4; nf++)
                #pragma unroll
                for (int c = 0; c < 4; c++) acc[mf][nf][c] = 0.f;

        #pragma unroll
        for (int ks = 0; ks < 8; ks++) {
            const uint32_t ko = (uint32_t)ks * 32;
            uint32_t ahi[2][4];
            #pragma unroll
            for (int mf = 0; mf < 2; mf++) {
                const uint32_t mo = (uint32_t)(mf * 16 * LDH) * 2;
                ldsm_x4(ahi[mf][0], ahi[mf][1], ahi[mf][2], ahi[mf][3], aHi + mo + ko);
            }
            #pragma unroll
            for (int nh = 0; nh < 2; nh++) {
                const uint32_t no = (uint32_t)(nh * 16 * LDH) * 2;
                uint32_t bh[4];
                ldsm_x4(bh[0], bh[1], bh[2], bh[3], bHi + no + ko);
                mma16816(acc[0][nh*2],     ahi[0], bh + 0);
                mma16816(acc[1][nh*2],     ahi[1], bh + 0);
                mma16816(acc[0][nh*2 + 1], ahi[0], bh + 2);
                mma16816(acc[1][nh*2 + 1], ahi[1], bh + 2);
                uint32_t bl[4];
                ldsm_x4(bl[0], bl[1], bl[2], bl[3], bLo + no + ko);
                mma16816(acc[0][nh*2],     ahi[0], bl + 0);
                mma16816(acc[1][nh*2],     ahi[1], bl + 0);
                mma16816(acc[0][nh*2 + 1], ahi[0], bl + 2);
                mma16816(acc[1][nh*2 + 1], ahi[1], bl + 2);
            }
        }
        __syncthreads();   // all ldsm done; Xhi free for next sub-tile

        // epilogue
        const float* ebj = g_eb[je];
        #pragma unroll
        for (int mf = 0; mf < 2; mf++) {
            const int r0 = row0 + wm * 32 + mf * 16 + (lane >> 2);
            const int r1 = r0 + 8;
            #pragma unroll
            for (int nf = 0; nf < 4; nf++) {
                const int col = wn * 32 + nf * 8 + 2 * (lane & 3);
                float e0 = __ldg(ebj + col), e1 = __ldg(ebj + col + 1);
                float v0 = acc[mf][nf][0] + e0, v1 = acc[mf][nf][1] + e1;
                float v2 = acc[mf][nf][2] + e0, v3 = acc[mf][nf][3] + e1;
                if (dotanh) { v0 = tanha(v0); v1 = tanha(v1); v2 = tanha(v2); v3 = tanha(v3); }
                if (r0 < M) *(__half2*)(outp + (size_t)r0 * D + col) = __floats2half2_rn(v0, v1);
                if (r1 < M) *(__half2*)(outp + (size_t)r1 * D + col) = __floats2half2_rn(v2, v3);
            }
        }
    }
}

// One warp per user; 4-step pipelined; fp32 dot, f16x2 tanh, fp32 accumulate.
__global__ void __launch_bounds__(256) attend_kernel(
    const int* __restrict__ item_seqs,
    const int* __restrict__ opin_seqs,
    float* __restrict__ out, int U, int L)
{
    const int gw   = (int)((blockIdx.x * blockDim.x + threadIdx.x) >> 5);
    const int lane = threadIdx.x & 31;
    if (gw >= U) return;

    const uint2* Kt = (const uint2*)g_Ktab;   // 32 uint2 per row
    const uint2* At = (const uint2*)g_A;
    const uint2* Bt = (const uint2*)g_B;

    uint2 qw = *((const uint2*)g_Q + (size_t)gw * 32 + lane);
    float2 q01 = __half22float2(*reinterpret_cast<__half2*>(&qw.x));
    float2 q23 = __half22float2(*reinterpret_cast<__half2*>(&qw.y));

    float4 acc = make_float4(0.f, 0.f, 0.f, 0.f);
    const int* is = item_seqs + (size_t)gw * L;
    const int* os = opin_seqs + (size_t)gw * L;

    const int Lm = L & ~3;
    for (int l = 0; l < Lm; l += 4) {
        int2 i01 = __ldg((const int2*)(is + l));
        int2 i23 = __ldg((const int2*)(is + l + 2));
        int2 o01 = __ldg((const int2*)(os + l));
        int2 o23 = __ldg((const int2*)(os + l + 2));
        int ii[4] = {i01.x, i01.y, i23.x, i23.y};
        int oo[4] = {o01.x, o01.y, o23.x, o23.y};

        uint2 kw[4], aw[4], bw[4];
        #pragma unroll
        for (int t = 0; t < 4; t++) {
            kw[t] = __ldg(Kt + (size_t)ii[t] * 32 + lane);
            aw[t] = __ldg(At + (size_t)ii[t] * 32 + lane);
            bw[t] = __ldg(Bt + (size_t)oo[t] * 32 + lane);
        }

        float w[4];
        #pragma unroll
        for (int t = 0; t < 4; t++) {
            float2 k01 = __half22float2(*reinterpret_cast<__half2*>(&kw[t].x));
            float2 k23 = __half22float2(*reinterpret_cast<__half2*>(&kw[t].y));
            w[t] = q01.x * k01.x + q01.y * k01.y + q23.x * k23.x + q23.y * k23.y;
        }
        #pragma unroll
        for (int s = 16; s; s >>= 1) {
            w[0] += __shfl_xor_sync(0xffffffffu, w[0], s);
            w[1] += __shfl_xor_sync(0xffffffffu, w[1], s);
            w[2] += __shfl_xor_sync(0xffffffffu, w[2], s);
            w[3] += __shfl_xor_sync(0xffffffffu, w[3], s);
        }
        #pragma unroll
        for (int t = 0; t < 4; t++) {
            float wt = (ii[t] > 0) ? w[t] : 0.f;
            __half2 sx = tanh2(__hadd2(*reinterpret_cast<__half2*>(&aw[t].x),
                                       *reinterpret_cast<__half2*>(&bw[t].x)));
            __half2 sy = tanh2(__hadd2(*reinterpret_cast<__half2*>(&aw[t].y),
                                       *reinterpret_cast<__half2*>(&bw[t].y)));
            float2 fx = __half22float2(sx), fy = __half22float2(sy);
            acc.x += wt * fx.x;
            acc.y += wt * fx.y;
            acc.z += wt * fy.x;
            acc.w += wt * fy.y;
        }
    }
    for (int l = Lm; l < L; ++l) {
        int i = __ldg(is + l);
        int o = __ldg(os + l);
        uint2 kw = __ldg(Kt + (size_t)i * 32 + lane);
        uint2 aw = __ldg(At + (size_t)i * 32 + lane);
        uint2 bw = __ldg(Bt + (size_t)o * 32 + lane);
        float2 k01 = __half22float2(*reinterpret_cast<__half2*>(&kw.x));
        float2 k23 = __half22float2(*reinterpret_cast<__half2*>(&kw.y));
        float w = q01.x * k01.x + q01.y * k01.y + q23.x * k23.x + q23.y * k23.y;
        #pragma unroll
        for (int s = 16; s; s >>= 1) w += __shfl_xor_sync(0xffffffffu, w, s);
        w = (i > 0) ? w : 0.f;
        __half2 sx = tanh2(__hadd2(*reinterpret_cast<__half2*>(&aw.x),
                                   *reinterpret_cast<__half2*>(&bw.x)));
        __half2 sy = tanh2(__hadd2(*reinterpret_cast<__half2*>(&aw.y),
                                   *reinterpret_cast<__half2*>(&bw.y)));
        float2 fx = __half22float2(sx), fy = __half22float2(sy);
        acc.x += w * fx.x;
        acc.y += w * fx.y;
        acc.z += w * fy.x;
        acc.w += w * fy.y;
    }
    *(float4*)(out + (size_t)gw * D + lane * 4) = acc;
}

extern "C" void kernel_launch(void* const* d_in, const int* in_sizes, int n_in,
                              void* d_out, int out_size)
{
    const float* item_table = (const float*)d_in[0];
    const float* opin_table = (const float*)d_in[1];
    const float* user_emb   = (const float*)d_in[2];
    const float* attr       = (const float*)d_in[3];
    const float* Wq         = (const float*)d_in[4];
    const float* bq         = (const float*)d_in[5];
    const float* Wk         = (const float*)d_in[6];
    const float* bk         = (const float*)d_in[7];
    const float* Wv         = (const float*)d_in[8];
    const float* bv         = (const float*)d_in[9];
    const int*   item_seqs  = (const int*)d_in[10];
    const int*   opin_seqs  = (const int*)d_in[11];
    float*       out        = (float*)d_out;

    const int n_item = in_sizes[0] / D;
    const int n_opi  = in_sizes[1] / D;
    const int U      = in_sizes[2] / D;
    const int L      = in_sizes[10] / U;

    __half *pK, *pA, *pB, *pQ;
    cudaGetSymbolAddress((void**)&pK, g_Ktab);
    cudaGetSymbolAddress((void**)&pA, g_A);
    cudaGetSymbolAddress((void**)&pB, g_B);
    cudaGetSymbolAddress((void**)&pQ, g_Q);

    const int nbK = (n_item + 255) / 256;
    const int nbA = nbK;
    const int nbB = (n_opi + 255) / 256;
    const int nbQ = (U + 255) / 256;

    const int smemB = 3 * TILE_B;   // 104448 B -> 2 CTAs/SM
    cudaFuncSetAttribute((const void*)tab_gemm_all,
                         cudaFuncAttributeMaxDynamicSharedMemorySize, smemB);

    setup_kernel<<<51, 256>>>(Wk, bk, Wv, bv, Wq, bq, attr);

    tab_gemm_all<<<nbK + nbA + nbB + nbQ, 512, smemB>>>(
        item_table, opin_table, user_emb,
        pK, pA, pB, pQ, n_item, n_opi, U, nbK, nbA, nbB);

    const int threads = 256;
    const int blocks  = (U * 32 + threads - 1) / threads;
    attend_kernel<<<blocks, threads>>>(item_seqs, opin_seqs, out, U, L);
}